// round 7
// baseline (speedup 1.0000x reference)
#include <cuda_runtime.h>

#define N_MAXN 100000
#define E_MAXE 3200000
#define HID 16
#define NC 40
#define F_IN 256

// Scratch (device globals -- no allocation allowed)
__device__ int   d_is64;                 // 1 if edge_index words are int64 pairs
__device__ int   d_cnt[N_MAXN];          // in-degree (excluding self-loop)
__device__ int   d_rowstart[N_MAXN];     // CSR row offsets
__device__ int   d_cursor[N_MAXN];       // fill cursors
__device__ int   d_perm[E_MAXE];         // src node per edge, sorted by dst
__device__ float d_dinv[N_MAXN];
__device__ __align__(16) float d_gA[N_MAXN * HID];  // dinv*(x@W1)
__device__ __align__(16) float d_gB[N_MAXN * HID];  // dinv*relu(...)
__device__ __align__(16) float d_agg[N_MAXN * HID]; // layer-2 aggregate

__device__ __forceinline__ int clampi(int v, int n) {
    return v < 0 ? 0 : (v >= n ? n - 1 : v);
}

// Launch 0: zero cnt (all blocks) + int64/int32 layout detect (block 0).
__global__ void k_init(const int* __restrict__ w, int nwords, int n) {
    int i = blockIdx.x * blockDim.x + threadIdx.x;
    if (i < n) d_cnt[i] = 0;
    if (blockIdx.x == 0) {
        __shared__ int anynz;
        if (threadIdx.x == 0) anynz = 0;
        __syncthreads();
        int limit = nwords < 8192 ? nwords : 8192;
        for (int k = threadIdx.x * 2 + 1; k < limit; k += 512)
            if (w[k] != 0) anynz = 1;
        __syncthreads();
        if (threadIdx.x == 0) d_is64 = anynz ? 0 : 1;
    }
}

// Launch 1: degree histogram. 2 edges per thread (vectorized on the i64 path).
__global__ void k_hist(const int* __restrict__ w, int E, int n) {
    int t = blockIdx.x * blockDim.x + threadIdx.x;
    int e = t * 2;
    if (e >= E) return;
    if (d_is64) {
        const longlong2* dst2 = (const longlong2*)((const long long*)w + E);
        longlong2 p = dst2[t];
        atomicAdd(&d_cnt[clampi((int)p.x, n)], 1);
        if (e + 1 < E) atomicAdd(&d_cnt[clampi((int)p.y, n)], 1);
    } else {
        atomicAdd(&d_cnt[clampi(w[E + e], n)], 1);
        if (e + 1 < E) atomicAdd(&d_cnt[clampi(w[E + e + 1], n)], 1);
    }
}

// Launch 2: single-block segmented exclusive scan; emits rowstart, cursor, dinv.
__global__ void k_scanall(int n) {
    __shared__ int s[1024];
    int t = threadIdx.x;
    int vpt = (n + 1023) / 1024;
    int lo = t * vpt;
    int hi = lo + vpt < n ? lo + vpt : n;
    int sum = 0;
    for (int i = lo; i < hi; i++) sum += d_cnt[i];
    s[t] = sum;
    __syncthreads();
    for (int off = 1; off < 1024; off <<= 1) {
        int u = (t >= off) ? s[t - off] : 0;
        __syncthreads();
        s[t] += u;
        __syncthreads();
    }
    int run = s[t] - sum;  // exclusive prefix of this thread's segment
    for (int i = lo; i < hi; i++) {
        int c = d_cnt[i];
        d_rowstart[i] = run;
        d_cursor[i] = run;
        d_dinv[i] = rsqrtf((float)c + 1.0f);
        run += c;
    }
}

// Launch 3: CSR fill (counting-sort of src by dst). 2 edges per thread.
__global__ void k_fill(const int* __restrict__ w, int E, int n) {
    int t = blockIdx.x * blockDim.x + threadIdx.x;
    int e = t * 2;
    if (e >= E) return;
    if (d_is64) {
        const longlong2* src2 = (const longlong2*)(const long long*)w;
        const longlong2* dst2 = (const longlong2*)((const long long*)w + E);
        longlong2 sp = src2[t];
        longlong2 dp = dst2[t];
        int p0 = atomicAdd(&d_cursor[clampi((int)dp.x, n)], 1);
        d_perm[p0] = clampi((int)sp.x, n);
        if (e + 1 < E) {
            int p1 = atomicAdd(&d_cursor[clampi((int)dp.y, n)], 1);
            d_perm[p1] = clampi((int)sp.y, n);
        }
    } else {
        int p0 = atomicAdd(&d_cursor[clampi(w[E + e], n)], 1);
        d_perm[p0] = clampi(w[e], n);
        if (e + 1 < E) {
            int p1 = atomicAdd(&d_cursor[clampi(w[E + e + 1], n)], 1);
            d_perm[p1] = clampi(w[e + 1], n);
        }
    }
}

// Launch 4: GEMM1: gA[i] = dinv[i] * (x[i] @ W1). 128 rows/block, 128 threads.
__global__ void k_gemm1(const float* __restrict__ x, const float* __restrict__ W1, int n) {
    __shared__ float W1s[F_IN * HID];   // 16 KB
    __shared__ float xs[128 * 33];      // padded
    int tid = threadIdx.x;
    for (int i = tid; i < F_IN * HID; i += 128) W1s[i] = W1[i];
    int row0 = blockIdx.x * 128;

    float acc[HID];
#pragma unroll
    for (int j = 0; j < HID; j++) acc[j] = 0.f;

    for (int kc = 0; kc < F_IN; kc += 32) {
        __syncthreads();
#pragma unroll
        for (int i = 0; i < 32; i++) {
            int lin = tid + 128 * i;
            int r = lin >> 5, k = lin & 31;
            int row = row0 + r;
            xs[r * 33 + k] = (row < n) ? x[(long long)row * F_IN + kc + k] : 0.f;
        }
        __syncthreads();
#pragma unroll
        for (int k = 0; k < 32; k++) {
            float xv = xs[tid * 33 + k];
            const float* w = &W1s[(kc + k) * HID];
#pragma unroll
            for (int j = 0; j < HID; j++) acc[j] = fmaf(xv, w[j], acc[j]);
        }
    }

    int row = row0 + tid;
    if (row < n) {
        float di = d_dinv[row];
        float4* g = (float4*)&d_gA[row * HID];
#pragma unroll
        for (int q = 0; q < 4; q++)
            g[q] = make_float4(di * acc[q * 4 + 0], di * acc[q * 4 + 1],
                               di * acc[q * 4 + 2], di * acc[q * 4 + 3]);
    }
}

// Launches 5,6: CSR gather. 4 threads per node, one float4 quad each.
// LAYER 0: reads gA, writes gB = dinv * relu(dinv*acc + b1)
// LAYER 1: reads gB, writes agg = acc (raw)
template <int LAYER>
__global__ void k_gather(const float* __restrict__ b1, int n) {
    int idx = blockIdx.x * blockDim.x + threadIdx.x;
    if (idx >= n * 4) return;
    int node = idx >> 2, q = idx & 3;
    const float4* __restrict__ g4 = (const float4*)(LAYER ? d_gB : d_gA);

    float4 acc = g4[node * 4 + q];  // self-loop term
    int start = d_rowstart[node];
    int end = start + d_cnt[node];
#pragma unroll 8
    for (int j = start; j < end; j++) {
        int s = __ldg(&d_perm[j]);
        float4 v = g4[s * 4 + q];
        acc.x += v.x; acc.y += v.y; acc.z += v.z; acc.w += v.w;
    }

    float di = d_dinv[node];
    if (LAYER == 0) {
        float4 b = ((const float4*)b1)[q];
        float4 h;
        h.x = di * fmaxf(fmaf(di, acc.x, b.x), 0.f);
        h.y = di * fmaxf(fmaf(di, acc.y, b.y), 0.f);
        h.z = di * fmaxf(fmaf(di, acc.z, b.z), 0.f);
        h.w = di * fmaxf(fmaf(di, acc.w, b.w), 0.f);
        ((float4*)d_gB)[idx] = h;
    } else {
        ((float4*)d_agg)[idx] = acc;
    }
}

// Launch 7: logits = (dinv*agg) @ W2 + b2; log_softmax.
__global__ void k_final(const float* __restrict__ W2, const float* __restrict__ b2,
                        float* __restrict__ out, int n) {
    __shared__ float W2s[HID * NC];
    __shared__ float b2s[NC];
    int tid = threadIdx.x;
    for (int i = tid; i < HID * NC; i += blockDim.x) W2s[i] = W2[i];
    if (tid < NC) b2s[tid] = b2[tid];
    __syncthreads();

    int i = blockIdx.x * blockDim.x + tid;
    if (i >= n) return;
    float di = d_dinv[i];
    float p[HID];
#pragma unroll
    for (int q = 0; q < 4; q++) {
        float4 v = ((const float4*)d_agg)[i * 4 + q];
        p[q * 4 + 0] = di * v.x;
        p[q * 4 + 1] = di * v.y;
        p[q * 4 + 2] = di * v.z;
        p[q * 4 + 3] = di * v.w;
    }
    float l[NC];
#pragma unroll
    for (int j = 0; j < NC; j++) l[j] = b2s[j];
#pragma unroll
    for (int k = 0; k < HID; k++) {
        float pk = p[k];
#pragma unroll
        for (int j = 0; j < NC; j++) l[j] = fmaf(pk, W2s[k * NC + j], l[j]);
    }
    float m = l[0];
#pragma unroll
    for (int j = 1; j < NC; j++) m = fmaxf(m, l[j]);
    float sum = 0.f;
#pragma unroll
    for (int j = 0; j < NC; j++) sum += __expf(l[j] - m);
    float lse = m + __logf(sum);
#pragma unroll
    for (int j = 0; j < NC; j++) out[(long long)i * NC + j] = l[j] - lse;
}

extern "C" void kernel_launch(void* const* d_in, const int* in_sizes, int n_in,
                              void* d_out, int out_size) {
    const float* x   = (const float*)d_in[0];
    const int*   eiw = (const int*)d_in[1];   // raw words; layout detected on device
    const float* W1  = (const float*)d_in[2];
    const float* b1  = (const float*)d_in[3];
    const float* W2  = (const float*)d_in[4];
    const float* b2  = (const float*)d_in[5];
    float* out = (float*)d_out;

    int n = in_sizes[0] / F_IN;        // 100000
    int E = in_sizes[1] / 2;           // 3200000
    int nwords = in_sizes[1] * 2;
    int eh = (E + 1) / 2;              // threads for 2-edge kernels

    k_init     <<<(n + 255) / 256, 256>>>(eiw, nwords, n);        // launch 0
    k_hist     <<<(eh + 255) / 256, 256>>>(eiw, E, n);            // launch 1
    k_scanall  <<<1, 1024>>>(n);                                  // launch 2
    k_fill     <<<(eh + 255) / 256, 256>>>(eiw, E, n);            // launch 3
    k_gemm1    <<<(n + 127) / 128, 128>>>(x, W1, n);              // launch 4
    k_gather<0><<<(n * 4 + 255) / 256, 256>>>(b1, n);             // launch 5 <- ncu captures this
    k_gather<1><<<(n * 4 + 255) / 256, 256>>>(b1, n);             // launch 6
    k_final    <<<(n + 127) / 128, 128>>>(W2, b2, out, n);        // launch 7
}

// round 8
// speedup vs baseline: 1.8529x; 1.8529x over previous
#include <cuda_runtime.h>

#define N_MAXN 100000
#define E_MAXE 3200000
#define HID 16
#define NC 40
#define F_IN 256
#define SCAN_B 256

// Scratch (device globals -- no allocation allowed)
__device__ int   d_is64;                 // 1 if edge_index words are int64 pairs
__device__ int   d_cnt[N_MAXN];          // in-degree (excluding self-loop)
__device__ int   d_rowstart[N_MAXN];     // CSR row offsets
__device__ int   d_cursor[N_MAXN];       // fill cursors
__device__ int   d_perm[E_MAXE];         // src node per edge, sorted by dst
__device__ int   d_bsum[1024];           // scan block sums
__device__ float d_dinv[N_MAXN];
__device__ __align__(16) float d_gA[N_MAXN * HID];  // dinv*(x@W1)
__device__ __align__(16) float d_gB[N_MAXN * HID];  // dinv*relu(...)

__device__ __forceinline__ int clampi(int v, int n) {
    return v < 0 ? 0 : (v >= n ? n - 1 : v);
}

// zero cnt (all blocks) + int64/int32 layout detect (block 0).
__global__ void k_init(const int* __restrict__ w, int nwords, int n) {
    int i = blockIdx.x * blockDim.x + threadIdx.x;
    if (i < n) d_cnt[i] = 0;
    if (blockIdx.x == 0) {
        __shared__ int anynz;
        if (threadIdx.x == 0) anynz = 0;
        __syncthreads();
        int limit = nwords < 8192 ? nwords : 8192;
        for (int k = threadIdx.x * 2 + 1; k < limit; k += 512)
            if (w[k] != 0) anynz = 1;
        __syncthreads();
        if (threadIdx.x == 0) d_is64 = anynz ? 0 : 1;
    }
}

// degree histogram, 2 edges per thread.
__global__ void k_hist(const int* __restrict__ w, int E, int n) {
    int t = blockIdx.x * blockDim.x + threadIdx.x;
    int e = t * 2;
    if (e >= E) return;
    if (d_is64) {
        const longlong2* dst2 = (const longlong2*)((const long long*)w + E);
        longlong2 p = dst2[t];
        atomicAdd(&d_cnt[clampi((int)p.x, n)], 1);
        if (e + 1 < E) atomicAdd(&d_cnt[clampi((int)p.y, n)], 1);
    } else {
        atomicAdd(&d_cnt[clampi(w[E + e], n)], 1);
        if (e + 1 < E) atomicAdd(&d_cnt[clampi(w[E + e + 1], n)], 1);
    }
}

// Coalesced 3-phase scan (reverted from single-block version -- that serialized
// ~400K uncoalesced accesses on one SM and cost ~200us).
__global__ void k_scan1(int n) {
    __shared__ int s[SCAN_B];
    int i = blockIdx.x * SCAN_B + threadIdx.x;
    int v = (i < n) ? d_cnt[i] : 0;
    s[threadIdx.x] = v;
    __syncthreads();
    for (int off = 1; off < SCAN_B; off <<= 1) {
        int t = (threadIdx.x >= off) ? s[threadIdx.x - off] : 0;
        __syncthreads();
        s[threadIdx.x] += t;
        __syncthreads();
    }
    if (i < n) d_rowstart[i] = s[threadIdx.x] - v;
    if (threadIdx.x == SCAN_B - 1) d_bsum[blockIdx.x] = s[SCAN_B - 1];
}

__global__ void k_scan2(int nb) {
    __shared__ int s[1024];
    int t = threadIdx.x;
    int v = (t < nb) ? d_bsum[t] : 0;
    s[t] = v;
    __syncthreads();
    for (int off = 1; off < 1024; off <<= 1) {
        int u = (t >= off) ? s[t - off] : 0;
        __syncthreads();
        s[t] += u;
        __syncthreads();
    }
    if (t < nb) d_bsum[t] = s[t] - v;
}

__global__ void k_scan3(int n) {
    int i = blockIdx.x * blockDim.x + threadIdx.x;
    if (i < n) {
        int start = d_rowstart[i] + d_bsum[i / SCAN_B];
        d_rowstart[i] = start;
        d_cursor[i] = start;
        d_dinv[i] = rsqrtf((float)d_cnt[i] + 1.0f);
    }
}

// CSR fill (counting-sort of src by dst), 2 edges per thread.
__global__ void k_fill(const int* __restrict__ w, int E, int n) {
    int t = blockIdx.x * blockDim.x + threadIdx.x;
    int e = t * 2;
    if (e >= E) return;
    if (d_is64) {
        const longlong2* src2 = (const longlong2*)(const long long*)w;
        const longlong2* dst2 = (const longlong2*)((const long long*)w + E);
        longlong2 sp = src2[t];
        longlong2 dp = dst2[t];
        int p0 = atomicAdd(&d_cursor[clampi((int)dp.x, n)], 1);
        d_perm[p0] = clampi((int)sp.x, n);
        if (e + 1 < E) {
            int p1 = atomicAdd(&d_cursor[clampi((int)dp.y, n)], 1);
            d_perm[p1] = clampi((int)sp.y, n);
        }
    } else {
        int p0 = atomicAdd(&d_cursor[clampi(w[E + e], n)], 1);
        d_perm[p0] = clampi(w[e], n);
        if (e + 1 < E) {
            int p1 = atomicAdd(&d_cursor[clampi(w[E + e + 1], n)], 1);
            d_perm[p1] = clampi(w[e + 1], n);
        }
    }
}

// GEMM1: gA[i] = dinv[i] * (x[i] @ W1). 128 rows/block, 128 threads.
__global__ void k_gemm1(const float* __restrict__ x, const float* __restrict__ W1, int n) {
    __shared__ float W1s[F_IN * HID];   // 16 KB
    __shared__ float xs[128 * 33];      // padded
    int tid = threadIdx.x;
    for (int i = tid; i < F_IN * HID; i += 128) W1s[i] = W1[i];
    int row0 = blockIdx.x * 128;

    float acc[HID];
#pragma unroll
    for (int j = 0; j < HID; j++) acc[j] = 0.f;

    for (int kc = 0; kc < F_IN; kc += 32) {
        __syncthreads();
#pragma unroll
        for (int i = 0; i < 32; i++) {
            int lin = tid + 128 * i;
            int r = lin >> 5, k = lin & 31;
            int row = row0 + r;
            xs[r * 33 + k] = (row < n) ? x[(long long)row * F_IN + kc + k] : 0.f;
        }
        __syncthreads();
#pragma unroll
        for (int k = 0; k < 32; k++) {
            float xv = xs[tid * 33 + k];
            const float* w = &W1s[(kc + k) * HID];
#pragma unroll
            for (int j = 0; j < HID; j++) acc[j] = fmaf(xv, w[j], acc[j]);
        }
    }

    int row = row0 + tid;
    if (row < n) {
        float di = d_dinv[row];
        float4* g = (float4*)&d_gA[row * HID];
#pragma unroll
        for (int q = 0; q < 4; q++)
            g[q] = make_float4(di * acc[q * 4 + 0], di * acc[q * 4 + 1],
                               di * acc[q * 4 + 2], di * acc[q * 4 + 3]);
    }
}

// Layer-1 gather: 4 threads/node; gB = dinv * relu(dinv*acc + b1).
__global__ void k_gather0(const float* __restrict__ b1, int n) {
    int idx = blockIdx.x * blockDim.x + threadIdx.x;
    if (idx >= n * 4) return;
    int node = idx >> 2, q = idx & 3;
    const float4* __restrict__ g4 = (const float4*)d_gA;

    float4 acc = g4[node * 4 + q];  // self-loop
    int start = d_rowstart[node];
    int end = start + d_cnt[node];
#pragma unroll 8
    for (int j = start; j < end; j++) {
        int s = __ldg(&d_perm[j]);
        float4 v = g4[s * 4 + q];
        acc.x += v.x; acc.y += v.y; acc.z += v.z; acc.w += v.w;
    }

    float di = d_dinv[node];
    float4 b = ((const float4*)b1)[q];
    float4 h;
    h.x = di * fmaxf(fmaf(di, acc.x, b.x), 0.f);
    h.y = di * fmaxf(fmaf(di, acc.y, b.y), 0.f);
    h.z = di * fmaxf(fmaf(di, acc.z, b.z), 0.f);
    h.w = di * fmaxf(fmaf(di, acc.w, b.w), 0.f);
    ((float4*)d_gB)[idx] = h;
}

// Layer-2 gather fused with logits + log_softmax.
// Phase A: 4 threads/node accumulate p = dinv*agg into smem.
// Phase B: each of the 4 threads computes 10 of the 40 logits; max/sum reduced
// across the 4-lane group with shfl_xor; 10 outputs stored per thread.
__global__ void k_gather1_final(const float* __restrict__ W2, const float* __restrict__ b2,
                                float* __restrict__ out, int n) {
    __shared__ float W2s[HID * NC];
    __shared__ float b2s[NC];
    __shared__ float hs[64 * 17];       // 64 nodes/block, padded stride 17
    int tid = threadIdx.x;
    for (int i = tid; i < HID * NC; i += 256) W2s[i] = W2[i];
    if (tid < NC) b2s[tid] = b2[tid];

    int idx = blockIdx.x * 256 + tid;
    int node = idx >> 2, q = idx & 3;
    int ln = tid >> 2;                  // local node 0..63

    if (node < n) {
        const float4* __restrict__ g4 = (const float4*)d_gB;
        float4 acc = g4[node * 4 + q];  // self-loop
        int start = d_rowstart[node];
        int end = start + d_cnt[node];
#pragma unroll 8
        for (int j = start; j < end; j++) {
            int s = __ldg(&d_perm[j]);
            float4 v = g4[s * 4 + q];
            acc.x += v.x; acc.y += v.y; acc.z += v.z; acc.w += v.w;
        }
        float di = d_dinv[node];
        hs[ln * 17 + q * 4 + 0] = di * acc.x;
        hs[ln * 17 + q * 4 + 1] = di * acc.y;
        hs[ln * 17 + q * 4 + 2] = di * acc.z;
        hs[ln * 17 + q * 4 + 3] = di * acc.w;
    }
    __syncthreads();

    // Phase B: all threads execute (shfl needs full warps); stores guarded.
    float p[HID];
#pragma unroll
    for (int k = 0; k < HID; k++) p[k] = hs[ln * 17 + k];

    float l[10];
#pragma unroll
    for (int j = 0; j < 10; j++) {
        int col = q * 10 + j;
        float a = b2s[col];
#pragma unroll
        for (int k = 0; k < HID; k++) a = fmaf(p[k], W2s[k * NC + col], a);
        l[j] = a;
    }
    float m = l[0];
#pragma unroll
    for (int j = 1; j < 10; j++) m = fmaxf(m, l[j]);
    m = fmaxf(m, __shfl_xor_sync(0xffffffffu, m, 1));
    m = fmaxf(m, __shfl_xor_sync(0xffffffffu, m, 2));
    float s = 0.f;
#pragma unroll
    for (int j = 0; j < 10; j++) s += __expf(l[j] - m);
    s += __shfl_xor_sync(0xffffffffu, s, 1);
    s += __shfl_xor_sync(0xffffffffu, s, 2);
    float lse = m + __logf(s);

    if (node < n) {
        float* o = out + (long long)node * NC + q * 10;
#pragma unroll
        for (int j = 0; j < 10; j++) o[j] = l[j] - lse;
    }
}

extern "C" void kernel_launch(void* const* d_in, const int* in_sizes, int n_in,
                              void* d_out, int out_size) {
    const float* x   = (const float*)d_in[0];
    const int*   eiw = (const int*)d_in[1];   // raw words; layout detected on device
    const float* W1  = (const float*)d_in[2];
    const float* b1  = (const float*)d_in[3];
    const float* W2  = (const float*)d_in[4];
    const float* b2  = (const float*)d_in[5];
    float* out = (float*)d_out;

    int n = in_sizes[0] / F_IN;        // 100000
    int E = in_sizes[1] / 2;           // 3200000
    int nwords = in_sizes[1] * 2;
    int eh = (E + 1) / 2;
    int nb = (n + SCAN_B - 1) / SCAN_B;

    k_init  <<<(n + 255) / 256, 256>>>(eiw, nwords, n);
    k_hist  <<<(eh + 255) / 256, 256>>>(eiw, E, n);
    k_scan1 <<<nb, SCAN_B>>>(n);
    k_scan2 <<<1, 1024>>>(nb);
    k_scan3 <<<(n + 255) / 256, 256>>>(n);
    k_fill  <<<(eh + 255) / 256, 256>>>(eiw, E, n);
    k_gemm1 <<<(n + 127) / 128, 128>>>(x, W1, n);
    k_gather0<<<(n * 4 + 255) / 256, 256>>>(b1, n);
    k_gather1_final<<<(n * 4 + 255) / 256, 256>>>(W2, b2, out, n);
}

// round 9
// speedup vs baseline: 2.3863x; 1.2879x over previous
#include <cuda_runtime.h>

#define N_MAXN 100000
#define E_MAXE 3200000
#define HID 16
#define NC 40
#define F_IN 256
#define SCAN_B 256
#define NB_MAX 1024

// Scratch (device globals -- no allocation allowed)
__device__ int   d_is64;                 // 1 if edge_index words are int64 pairs
__device__ int   d_cnt[N_MAXN];          // in-degree (excluding self-loop)
__device__ int   d_rowstart[N_MAXN];     // CSR row offsets
__device__ int   d_cursor[N_MAXN];       // fill cursors
__device__ int   d_perm[E_MAXE];         // src node per edge, sorted by dst
__device__ unsigned long long d_bstate[NB_MAX];  // lookback: (flag<<62)|value
__device__ float d_dinv[N_MAXN];
__device__ __align__(16) float d_gA[N_MAXN * HID];  // dinv*(x@W1)
__device__ __align__(16) float d_gB[N_MAXN * HID];  // dinv*relu(...)

__device__ __forceinline__ int clampi(int v, int n) {
    return v < 0 ? 0 : (v >= n ? n - 1 : v);
}

// zero cnt + lookback state (all blocks) + int64/int32 layout detect (block 0).
__global__ void k_init(const int* __restrict__ w, int nwords, int n) {
    int i = blockIdx.x * blockDim.x + threadIdx.x;
    if (i < n) d_cnt[i] = 0;
    if (i < NB_MAX) d_bstate[i] = 0ull;
    if (blockIdx.x == 0) {
        __shared__ int anynz;
        if (threadIdx.x == 0) anynz = 0;
        __syncthreads();
        int limit = nwords < 8192 ? nwords : 8192;
        for (int k = threadIdx.x * 2 + 1; k < limit; k += 512)
            if (w[k] != 0) anynz = 1;
        __syncthreads();
        if (threadIdx.x == 0) d_is64 = anynz ? 0 : 1;
    }
}

// degree histogram, 2 edges per thread.
__global__ void k_hist(const int* __restrict__ w, int E, int n) {
    int t = blockIdx.x * blockDim.x + threadIdx.x;
    int e = t * 2;
    if (e >= E) return;
    if (d_is64) {
        const longlong2* dst2 = (const longlong2*)((const long long*)w + E);
        longlong2 p = dst2[t];
        atomicAdd(&d_cnt[clampi((int)p.x, n)], 1);
        if (e + 1 < E) atomicAdd(&d_cnt[clampi((int)p.y, n)], 1);
    } else {
        atomicAdd(&d_cnt[clampi(w[E + e], n)], 1);
        if (e + 1 < E) atomicAdd(&d_cnt[clampi(w[E + e + 1], n)], 1);
    }
}

// Single-pass scan with decoupled lookback. Emits rowstart, cursor, dinv.
// Per-block state is one 64-bit word: flag in bits[62:64) (1=aggregate,
// 2=inclusive prefix), value in low bits -- a single volatile 64-bit load
// observes flag+value atomically, so no fences are needed on the read side.
__global__ void k_scan(int n) {
    __shared__ int s[SCAN_B];
    __shared__ int s_exc;
    int b = blockIdx.x, t = threadIdx.x;
    int i = b * SCAN_B + t;
    int v = (i < n) ? d_cnt[i] : 0;
    s[t] = v;
    __syncthreads();
    for (int off = 1; off < SCAN_B; off <<= 1) {
        int u = (t >= off) ? s[t - off] : 0;
        __syncthreads();
        s[t] += u;
        __syncthreads();
    }
    if (t == 0) {
        int total = s[SCAN_B - 1];
        volatile unsigned long long* st = (volatile unsigned long long*)d_bstate;
        st[b] = (1ull << 62) | (unsigned long long)total;
        int exc = 0;
        for (int p = b - 1; p >= 0; --p) {
            unsigned long long f;
            do { f = st[p]; } while (f == 0ull);
            exc += (int)(f & 0xffffffffull);
            if ((f >> 62) == 2ull) break;
        }
        st[b] = (2ull << 62) | (unsigned long long)(exc + total);
        s_exc = exc;
    }
    __syncthreads();
    if (i < n) {
        int start = s_exc + s[t] - v;   // exclusive
        d_rowstart[i] = start;
        d_cursor[i] = start;
        d_dinv[i] = rsqrtf((float)v + 1.0f);
    }
}

// CSR fill (counting-sort of src by dst), 2 edges per thread.
__global__ void k_fill(const int* __restrict__ w, int E, int n) {
    int t = blockIdx.x * blockDim.x + threadIdx.x;
    int e = t * 2;
    if (e >= E) return;
    if (d_is64) {
        const longlong2* src2 = (const longlong2*)(const long long*)w;
        const longlong2* dst2 = (const longlong2*)((const long long*)w + E);
        longlong2 sp = src2[t];
        longlong2 dp = dst2[t];
        int p0 = atomicAdd(&d_cursor[clampi((int)dp.x, n)], 1);
        d_perm[p0] = clampi((int)sp.x, n);
        if (e + 1 < E) {
            int p1 = atomicAdd(&d_cursor[clampi((int)dp.y, n)], 1);
            d_perm[p1] = clampi((int)sp.y, n);
        }
    } else {
        int p0 = atomicAdd(&d_cursor[clampi(w[E + e], n)], 1);
        d_perm[p0] = clampi(w[e], n);
        if (e + 1 < E) {
            int p1 = atomicAdd(&d_cursor[clampi(w[E + e + 1], n)], 1);
            d_perm[p1] = clampi(w[e + 1], n);
        }
    }
}

// GEMM1: gA[i] = dinv[i] * (x[i] @ W1). 128 rows/block, 128 threads.
// Inner loop uses packed fma.rn.f32x2 (2x fp32 FMA throughput vs scalar FFMA).
__global__ void k_gemm1(const float* __restrict__ x, const float* __restrict__ W1, int n) {
    __shared__ float W1s[F_IN * HID];   // 16 KB
    __shared__ float xs[128 * 33];      // padded
    int tid = threadIdx.x;
    for (int i = tid; i < F_IN * HID; i += 128) W1s[i] = W1[i];
    int row0 = blockIdx.x * 128;

    unsigned long long acc2[8];         // 16 fp32 accumulators, packed f32x2
#pragma unroll
    for (int j = 0; j < 8; j++) acc2[j] = 0ull;

    for (int kc = 0; kc < F_IN; kc += 32) {
        __syncthreads();
#pragma unroll
        for (int i = 0; i < 32; i++) {
            int lin = tid + 128 * i;
            int r = lin >> 5, k = lin & 31;
            int row = row0 + r;
            xs[r * 33 + k] = (row < n) ? x[(long long)row * F_IN + kc + k] : 0.f;
        }
        __syncthreads();
#pragma unroll
        for (int k = 0; k < 32; k++) {
            unsigned int xu = __float_as_uint(xs[tid * 33 + k]);
            unsigned long long xv2;
            asm("mov.b64 %0, {%1, %2};" : "=l"(xv2) : "r"(xu), "r"(xu));
            const unsigned long long* w2 =
                (const unsigned long long*)&W1s[(kc + k) * HID];
#pragma unroll
            for (int j = 0; j < 8; j++)
                asm("fma.rn.f32x2 %0, %1, %2, %0;"
                    : "+l"(acc2[j]) : "l"(xv2), "l"(w2[j]));
        }
    }

    int row = row0 + tid;
    if (row < n) {
        float di = d_dinv[row];
        float4* g = (float4*)&d_gA[row * HID];
#pragma unroll
        for (int q = 0; q < 4; q++) {
            unsigned int a0, a1, b0, b1;
            asm("mov.b64 {%0, %1}, %2;" : "=r"(a0), "=r"(a1) : "l"(acc2[q * 2]));
            asm("mov.b64 {%0, %1}, %2;" : "=r"(b0), "=r"(b1) : "l"(acc2[q * 2 + 1]));
            g[q] = make_float4(di * __uint_as_float(a0), di * __uint_as_float(a1),
                               di * __uint_as_float(b0), di * __uint_as_float(b1));
        }
    }
}

// Layer-1 gather: 4 threads/node; gB = dinv * relu(dinv*acc + b1).
__global__ void k_gather0(const float* __restrict__ b1, int n) {
    int idx = blockIdx.x * blockDim.x + threadIdx.x;
    if (idx >= n * 4) return;
    int node = idx >> 2, q = idx & 3;
    const float4* __restrict__ g4 = (const float4*)d_gA;

    float4 acc = g4[node * 4 + q];  // self-loop
    int start = d_rowstart[node];
    int end = start + d_cnt[node];
#pragma unroll 8
    for (int j = start; j < end; j++) {
        int s = __ldg(&d_perm[j]);
        float4 v = g4[s * 4 + q];
        acc.x += v.x; acc.y += v.y; acc.z += v.z; acc.w += v.w;
    }

    float di = d_dinv[node];
    float4 b = ((const float4*)b1)[q];
    float4 h;
    h.x = di * fmaxf(fmaf(di, acc.x, b.x), 0.f);
    h.y = di * fmaxf(fmaf(di, acc.y, b.y), 0.f);
    h.z = di * fmaxf(fmaf(di, acc.z, b.z), 0.f);
    h.w = di * fmaxf(fmaf(di, acc.w, b.w), 0.f);
    ((float4*)d_gB)[idx] = h;
}

// Layer-2 gather fused with logits + log_softmax.
__global__ void k_gather1_final(const float* __restrict__ W2, const float* __restrict__ b2,
                                float* __restrict__ out, int n) {
    __shared__ float W2s[HID * NC];
    __shared__ float b2s[NC];
    __shared__ float hs[64 * 17];       // 64 nodes/block, padded stride 17
    int tid = threadIdx.x;
    for (int i = tid; i < HID * NC; i += 256) W2s[i] = W2[i];
    if (tid < NC) b2s[tid] = b2[tid];

    int idx = blockIdx.x * 256 + tid;
    int node = idx >> 2, q = idx & 3;
    int ln = tid >> 2;                  // local node 0..63

    if (node < n) {
        const float4* __restrict__ g4 = (const float4*)d_gB;
        float4 acc = g4[node * 4 + q];  // self-loop
        int start = d_rowstart[node];
        int end = start + d_cnt[node];
#pragma unroll 8
        for (int j = start; j < end; j++) {
            int s = __ldg(&d_perm[j]);
            float4 v = g4[s * 4 + q];
            acc.x += v.x; acc.y += v.y; acc.z += v.z; acc.w += v.w;
        }
        float di = d_dinv[node];
        hs[ln * 17 + q * 4 + 0] = di * acc.x;
        hs[ln * 17 + q * 4 + 1] = di * acc.y;
        hs[ln * 17 + q * 4 + 2] = di * acc.z;
        hs[ln * 17 + q * 4 + 3] = di * acc.w;
    }
    __syncthreads();

    float p[HID];
#pragma unroll
    for (int k = 0; k < HID; k++) p[k] = hs[ln * 17 + k];

    float l[10];
#pragma unroll
    for (int j = 0; j < 10; j++) {
        int col = q * 10 + j;
        float a = b2s[col];
#pragma unroll
        for (int k = 0; k < HID; k++) a = fmaf(p[k], W2s[k * NC + col], a);
        l[j] = a;
    }
    float m = l[0];
#pragma unroll
    for (int j = 1; j < 10; j++) m = fmaxf(m, l[j]);
    m = fmaxf(m, __shfl_xor_sync(0xffffffffu, m, 1));
    m = fmaxf(m, __shfl_xor_sync(0xffffffffu, m, 2));
    float s = 0.f;
#pragma unroll
    for (int j = 0; j < 10; j++) s += __expf(l[j] - m);
    s += __shfl_xor_sync(0xffffffffu, s, 1);
    s += __shfl_xor_sync(0xffffffffu, s, 2);
    float lse = m + __logf(s);

    if (node < n) {
        float* o = out + (long long)node * NC + q * 10;
#pragma unroll
        for (int j = 0; j < 10; j++) o[j] = l[j] - lse;
    }
}

extern "C" void kernel_launch(void* const* d_in, const int* in_sizes, int n_in,
                              void* d_out, int out_size) {
    const float* x   = (const float*)d_in[0];
    const int*   eiw = (const int*)d_in[1];   // raw words; layout detected on device
    const float* W1  = (const float*)d_in[2];
    const float* b1  = (const float*)d_in[3];
    const float* W2  = (const float*)d_in[4];
    const float* b2  = (const float*)d_in[5];
    float* out = (float*)d_out;

    int n = in_sizes[0] / F_IN;        // 100000
    int E = in_sizes[1] / 2;           // 3200000
    int nwords = in_sizes[1] * 2;
    int eh = (E + 1) / 2;
    int nb = (n + SCAN_B - 1) / SCAN_B;   // 391 <= NB_MAX

    k_init  <<<(n + 255) / 256, 256>>>(eiw, nwords, n);          // 0
    k_hist  <<<(eh + 255) / 256, 256>>>(eiw, E, n);              // 1
    k_scan  <<<nb, SCAN_B>>>(n);                                  // 2
    k_fill  <<<(eh + 255) / 256, 256>>>(eiw, E, n);              // 3
    k_gemm1 <<<(n + 127) / 128, 128>>>(x, W1, n);                // 4
    k_gather0<<<(n * 4 + 255) / 256, 256>>>(b1, n);              // 5 <- ncu
    k_gather1_final<<<(n * 4 + 255) / 256, 256>>>(W2, b2, out, n); // 6
}

// round 10
// speedup vs baseline: 2.4690x; 1.0346x over previous
#include <cuda_runtime.h>

#define N_MAXN 100000
#define E_MAXE 3200000
#define HID 16
#define NC 40
#define F_IN 256
#define SCAN_B 256
#define NB_MAX 1024

// Scratch (device globals -- no allocation allowed)
__device__ int   d_is64;                 // 1 if edge_index words are int64 pairs
__device__ int   d_cnt[N_MAXN];          // in-degree (excluding self-loop)
__device__ int   d_rowstart[N_MAXN];     // CSR row offsets
__device__ int   d_cursor[N_MAXN];       // fill cursors
__device__ int   d_perm[E_MAXE];         // src node per edge, sorted by dst
__device__ unsigned long long d_bstate[NB_MAX];  // lookback: (flag<<62)|value
__device__ float d_dinv[N_MAXN];
__device__ __align__(16) float d_gA[N_MAXN * HID];  // dinv*(x@W1)
__device__ __align__(16) float d_gB[N_MAXN * HID];  // dinv*relu(...)

__device__ __forceinline__ int clampi(int v, int n) {
    return v < 0 ? 0 : (v >= n ? n - 1 : v);
}

// zero cnt + lookback state (all blocks) + int64/int32 layout detect (block 0).
__global__ void k_init(const int* __restrict__ w, int nwords, int n) {
    int i = blockIdx.x * blockDim.x + threadIdx.x;
    if (i < n) d_cnt[i] = 0;
    if (i < NB_MAX) d_bstate[i] = 0ull;
    if (blockIdx.x == 0) {
        __shared__ int anynz;
        if (threadIdx.x == 0) anynz = 0;
        __syncthreads();
        int limit = nwords < 8192 ? nwords : 8192;
        for (int k = threadIdx.x * 2 + 1; k < limit; k += 512)
            if (w[k] != 0) anynz = 1;
        __syncthreads();
        if (threadIdx.x == 0) d_is64 = anynz ? 0 : 1;
    }
}

// degree histogram, 4 edges per thread (vectorized 32B index loads).
__global__ void k_hist(const int* __restrict__ w, int E, int n) {
    int t = blockIdx.x * blockDim.x + threadIdx.x;
    int e = t * 4;
    if (e >= E) return;
    if (d_is64) {
        const long long* dst = (const long long*)w + E;
        if (e + 3 < E) {
            longlong2 p0 = *(const longlong2*)(dst + e);
            longlong2 p1 = *(const longlong2*)(dst + e + 2);
            atomicAdd(&d_cnt[clampi((int)p0.x, n)], 1);
            atomicAdd(&d_cnt[clampi((int)p0.y, n)], 1);
            atomicAdd(&d_cnt[clampi((int)p1.x, n)], 1);
            atomicAdd(&d_cnt[clampi((int)p1.y, n)], 1);
        } else {
            for (int k = e; k < E; k++)
                atomicAdd(&d_cnt[clampi((int)dst[k], n)], 1);
        }
    } else {
        if (e + 3 < E) {
            int4 p = *(const int4*)(w + E + e);
            atomicAdd(&d_cnt[clampi(p.x, n)], 1);
            atomicAdd(&d_cnt[clampi(p.y, n)], 1);
            atomicAdd(&d_cnt[clampi(p.z, n)], 1);
            atomicAdd(&d_cnt[clampi(p.w, n)], 1);
        } else {
            for (int k = e; k < E; k++)
                atomicAdd(&d_cnt[clampi(w[E + k], n)], 1);
        }
    }
}

// Single-pass scan with decoupled lookback. Emits rowstart, cursor, dinv.
__global__ void k_scan(int n) {
    __shared__ int s[SCAN_B];
    __shared__ int s_exc;
    int b = blockIdx.x, t = threadIdx.x;
    int i = b * SCAN_B + t;
    int v = (i < n) ? d_cnt[i] : 0;
    s[t] = v;
    __syncthreads();
    for (int off = 1; off < SCAN_B; off <<= 1) {
        int u = (t >= off) ? s[t - off] : 0;
        __syncthreads();
        s[t] += u;
        __syncthreads();
    }
    if (t == 0) {
        int total = s[SCAN_B - 1];
        volatile unsigned long long* st = (volatile unsigned long long*)d_bstate;
        st[b] = (1ull << 62) | (unsigned long long)total;
        int exc = 0;
        for (int p = b - 1; p >= 0; --p) {
            unsigned long long f;
            do { f = st[p]; } while (f == 0ull);
            exc += (int)(f & 0xffffffffull);
            if ((f >> 62) == 2ull) break;
        }
        st[b] = (2ull << 62) | (unsigned long long)(exc + total);
        s_exc = exc;
    }
    __syncthreads();
    if (i < n) {
        int start = s_exc + s[t] - v;   // exclusive
        d_rowstart[i] = start;
        d_cursor[i] = start;
        d_dinv[i] = rsqrtf((float)v + 1.0f);
    }
}

// GEMM1: gA[i] = dinv[i] * (x[i] @ W1). 128 rows/block, 128 threads.
// Inner loop uses packed fma.rn.f32x2 (2x fp32 FMA throughput vs scalar FFMA).
__global__ void k_gemm1(const float* __restrict__ x, const float* __restrict__ W1, int n) {
    __shared__ float W1s[F_IN * HID];   // 16 KB
    __shared__ float xs[128 * 33];      // padded
    int tid = threadIdx.x;
    for (int i = tid; i < F_IN * HID; i += 128) W1s[i] = W1[i];
    int row0 = blockIdx.x * 128;

    unsigned long long acc2[8];         // 16 fp32 accumulators, packed f32x2
#pragma unroll
    for (int j = 0; j < 8; j++) acc2[j] = 0ull;

    for (int kc = 0; kc < F_IN; kc += 32) {
        __syncthreads();
#pragma unroll
        for (int i = 0; i < 32; i++) {
            int lin = tid + 128 * i;
            int r = lin >> 5, k = lin & 31;
            int row = row0 + r;
            xs[r * 33 + k] = (row < n) ? x[(long long)row * F_IN + kc + k] : 0.f;
        }
        __syncthreads();
#pragma unroll
        for (int k = 0; k < 32; k++) {
            unsigned int xu = __float_as_uint(xs[tid * 33 + k]);
            unsigned long long xv2;
            asm("mov.b64 %0, {%1, %2};" : "=l"(xv2) : "r"(xu), "r"(xu));
            const unsigned long long* w2 =
                (const unsigned long long*)&W1s[(kc + k) * HID];
#pragma unroll
            for (int j = 0; j < 8; j++)
                asm("fma.rn.f32x2 %0, %1, %2, %0;"
                    : "+l"(acc2[j]) : "l"(xv2), "l"(w2[j]));
        }
    }

    int row = row0 + tid;
    if (row < n) {
        float di = d_dinv[row];
        float4* g = (float4*)&d_gA[row * HID];
#pragma unroll
        for (int q = 0; q < 4; q++) {
            unsigned int a0, a1, b0, b1;
            asm("mov.b64 {%0, %1}, %2;" : "=r"(a0), "=r"(a1) : "l"(acc2[q * 2]));
            asm("mov.b64 {%0, %1}, %2;" : "=r"(b0), "=r"(b1) : "l"(acc2[q * 2 + 1]));
            g[q] = make_float4(di * __uint_as_float(a0), di * __uint_as_float(a1),
                               di * __uint_as_float(b0), di * __uint_as_float(b1));
        }
    }
}

// CSR fill (counting-sort of src by dst), 4 edges per thread.
__global__ void k_fill(const int* __restrict__ w, int E, int n) {
    int t = blockIdx.x * blockDim.x + threadIdx.x;
    int e = t * 4;
    if (e >= E) return;
    if (d_is64) {
        const long long* src = (const long long*)w;
        const long long* dst = src + E;
        if (e + 3 < E) {
            longlong2 s0 = *(const longlong2*)(src + e);
            longlong2 s1 = *(const longlong2*)(src + e + 2);
            longlong2 q0 = *(const longlong2*)(dst + e);
            longlong2 q1 = *(const longlong2*)(dst + e + 2);
            int p0 = atomicAdd(&d_cursor[clampi((int)q0.x, n)], 1);
            int p1 = atomicAdd(&d_cursor[clampi((int)q0.y, n)], 1);
            int p2 = atomicAdd(&d_cursor[clampi((int)q1.x, n)], 1);
            int p3 = atomicAdd(&d_cursor[clampi((int)q1.y, n)], 1);
            d_perm[p0] = clampi((int)s0.x, n);
            d_perm[p1] = clampi((int)s0.y, n);
            d_perm[p2] = clampi((int)s1.x, n);
            d_perm[p3] = clampi((int)s1.y, n);
        } else {
            for (int k = e; k < E; k++) {
                int p = atomicAdd(&d_cursor[clampi((int)dst[k], n)], 1);
                d_perm[p] = clampi((int)src[k], n);
            }
        }
    } else {
        if (e + 3 < E) {
            int4 sv = *(const int4*)(w + e);
            int4 dv = *(const int4*)(w + E + e);
            int p0 = atomicAdd(&d_cursor[clampi(dv.x, n)], 1);
            int p1 = atomicAdd(&d_cursor[clampi(dv.y, n)], 1);
            int p2 = atomicAdd(&d_cursor[clampi(dv.z, n)], 1);
            int p3 = atomicAdd(&d_cursor[clampi(dv.w, n)], 1);
            d_perm[p0] = clampi(sv.x, n);
            d_perm[p1] = clampi(sv.y, n);
            d_perm[p2] = clampi(sv.z, n);
            d_perm[p3] = clampi(sv.w, n);
        } else {
            for (int k = e; k < E; k++) {
                int p = atomicAdd(&d_cursor[clampi(w[E + k], n)], 1);
                d_perm[p] = clampi(w[k], n);
            }
        }
    }
}

// Layer-1 gather: 4 threads/node; gB = dinv * relu(dinv*acc + b1).
__global__ void k_gather0(const float* __restrict__ b1, int n) {
    int idx = blockIdx.x * blockDim.x + threadIdx.x;
    if (idx >= n * 4) return;
    int node = idx >> 2, q = idx & 3;
    const float4* __restrict__ g4 = (const float4*)d_gA;

    float4 acc = g4[node * 4 + q];  // self-loop
    int start = d_rowstart[node];
    int end = start + d_cnt[node];
#pragma unroll 8
    for (int j = start; j < end; j++) {
        int s = __ldg(&d_perm[j]);
        float4 v = g4[s * 4 + q];
        acc.x += v.x; acc.y += v.y; acc.z += v.z; acc.w += v.w;
    }

    float di = d_dinv[node];
    float4 b = ((const float4*)b1)[q];
    float4 h;
    h.x = di * fmaxf(fmaf(di, acc.x, b.x), 0.f);
    h.y = di * fmaxf(fmaf(di, acc.y, b.y), 0.f);
    h.z = di * fmaxf(fmaf(di, acc.z, b.z), 0.f);
    h.w = di * fmaxf(fmaf(di, acc.w, b.w), 0.f);
    ((float4*)d_gB)[idx] = h;
}

// Layer-2 gather fused with logits + log_softmax.
__global__ void k_gather1_final(const float* __restrict__ W2, const float* __restrict__ b2,
                                float* __restrict__ out, int n) {
    __shared__ float W2s[HID * NC];
    __shared__ float b2s[NC];
    __shared__ float hs[64 * 17];       // 64 nodes/block, padded stride 17
    int tid = threadIdx.x;
    for (int i = tid; i < HID * NC; i += 256) W2s[i] = W2[i];
    if (tid < NC) b2s[tid] = b2[tid];

    int idx = blockIdx.x * 256 + tid;
    int node = idx >> 2, q = idx & 3;
    int ln = tid >> 2;                  // local node 0..63

    if (node < n) {
        const float4* __restrict__ g4 = (const float4*)d_gB;
        float4 acc = g4[node * 4 + q];  // self-loop
        int start = d_rowstart[node];
        int end = start + d_cnt[node];
#pragma unroll 8
        for (int j = start; j < end; j++) {
            int s = __ldg(&d_perm[j]);
            float4 v = g4[s * 4 + q];
            acc.x += v.x; acc.y += v.y; acc.z += v.z; acc.w += v.w;
        }
        float di = d_dinv[node];
        hs[ln * 17 + q * 4 + 0] = di * acc.x;
        hs[ln * 17 + q * 4 + 1] = di * acc.y;
        hs[ln * 17 + q * 4 + 2] = di * acc.z;
        hs[ln * 17 + q * 4 + 3] = di * acc.w;
    }
    __syncthreads();

    float p[HID];
#pragma unroll
    for (int k = 0; k < HID; k++) p[k] = hs[ln * 17 + k];

    float l[10];
#pragma unroll
    for (int j = 0; j < 10; j++) {
        int col = q * 10 + j;
        float a = b2s[col];
#pragma unroll
        for (int k = 0; k < HID; k++) a = fmaf(p[k], W2s[k * NC + col], a);
        l[j] = a;
    }
    float m = l[0];
#pragma unroll
    for (int j = 1; j < 10; j++) m = fmaxf(m, l[j]);
    m = fmaxf(m, __shfl_xor_sync(0xffffffffu, m, 1));
    m = fmaxf(m, __shfl_xor_sync(0xffffffffu, m, 2));
    float s = 0.f;
#pragma unroll
    for (int j = 0; j < 10; j++) s += __expf(l[j] - m);
    s += __shfl_xor_sync(0xffffffffu, s, 1);
    s += __shfl_xor_sync(0xffffffffu, s, 2);
    float lse = m + __logf(s);

    if (node < n) {
        float* o = out + (long long)node * NC + q * 10;
#pragma unroll
        for (int j = 0; j < 10; j++) o[j] = l[j] - lse;
    }
}

extern "C" void kernel_launch(void* const* d_in, const int* in_sizes, int n_in,
                              void* d_out, int out_size) {
    const float* x   = (const float*)d_in[0];
    const int*   eiw = (const int*)d_in[1];   // raw words; layout detected on device
    const float* W1  = (const float*)d_in[2];
    const float* b1  = (const float*)d_in[3];
    const float* W2  = (const float*)d_in[4];
    const float* b2  = (const float*)d_in[5];
    float* out = (float*)d_out;

    int n = in_sizes[0] / F_IN;        // 100000
    int E = in_sizes[1] / 2;           // 3200000
    int nwords = in_sizes[1] * 2;
    int eh = (E + 3) / 4;              // 4 edges/thread
    int nb = (n + SCAN_B - 1) / SCAN_B;   // 391 <= NB_MAX

    k_init  <<<(n + 255) / 256, 256>>>(eiw, nwords, n);            // 0
    k_hist  <<<(eh + 255) / 256, 256>>>(eiw, E, n);                // 1
    k_scan  <<<nb, SCAN_B>>>(n);                                    // 2
    k_gemm1 <<<(n + 127) / 128, 128>>>(x, W1, n);                  // 3 <- ncu (index 3)
    k_fill  <<<(eh + 255) / 256, 256>>>(eiw, E, n);                // 4
    k_gather0<<<(n * 4 + 255) / 256, 256>>>(b1, n);                // 5
    k_gather1_final<<<(n * 4 + 255) / 256, 256>>>(W2, b2, out, n); // 6
}

// round 16
// speedup vs baseline: 2.4744x; 1.0022x over previous
#include <cuda_runtime.h>

#define N_MAXN 100000
#define E_MAXE 3200000
#define HID 16
#define NC 40
#define F_IN 256
#define SCAN_B 256
#define NB_MAX 1024

#define G1_THREADS 256
#define G1_ROWS 128
#define G1_KC 32
#define G1_CHUNKS (F_IN / G1_KC)
#define XS_PAD 34

// Scratch (device globals -- no allocation allowed)
__device__ int   d_is64;                 // 1 if edge_index words are int64 pairs
__device__ int   d_cnt[N_MAXN];          // in-degree (excluding self-loop)
__device__ int   d_rowstart[N_MAXN];     // CSR row offsets
__device__ int   d_cursor[N_MAXN];       // fill cursors
__device__ int   d_perm[E_MAXE];         // src node per edge, sorted by dst
__device__ unsigned long long d_bstate[NB_MAX];  // lookback: (flag<<62)|value
__device__ float d_dinv[N_MAXN];
__device__ __align__(16) float d_gA[N_MAXN * HID];  // dinv*(x@W1)
__device__ __align__(16) float d_gB[N_MAXN * HID];  // dinv*relu(...)

__device__ __forceinline__ int clampi(int v, int n) {
    return v < 0 ? 0 : (v >= n ? n - 1 : v);
}

// zero cnt + lookback state (all blocks) + int64/int32 layout detect (block 0).
__global__ void k_init(const int* __restrict__ w, int nwords, int n) {
    int i = blockIdx.x * blockDim.x + threadIdx.x;
    if (i < n) d_cnt[i] = 0;
    if (i < NB_MAX) d_bstate[i] = 0ull;
    if (blockIdx.x == 0) {
        __shared__ int anynz;
        if (threadIdx.x == 0) anynz = 0;
        __syncthreads();
        int limit = nwords < 8192 ? nwords : 8192;
        for (int k = threadIdx.x * 2 + 1; k < limit; k += 512)
            if (w[k] != 0) anynz = 1;
        __syncthreads();
        if (threadIdx.x == 0) d_is64 = anynz ? 0 : 1;
    }
}

// degree histogram, 4 edges per thread (vectorized 32B index loads).
__global__ void k_hist(const int* __restrict__ w, int E, int n) {
    int t = blockIdx.x * blockDim.x + threadIdx.x;
    int e = t * 4;
    if (e >= E) return;
    if (d_is64) {
        const long long* dst = (const long long*)w + E;
        if (e + 3 < E) {
            longlong2 p0 = *(const longlong2*)(dst + e);
            longlong2 p1 = *(const longlong2*)(dst + e + 2);
            atomicAdd(&d_cnt[clampi((int)p0.x, n)], 1);
            atomicAdd(&d_cnt[clampi((int)p0.y, n)], 1);
            atomicAdd(&d_cnt[clampi((int)p1.x, n)], 1);
            atomicAdd(&d_cnt[clampi((int)p1.y, n)], 1);
        } else {
            for (int k = e; k < E; k++)
                atomicAdd(&d_cnt[clampi((int)dst[k], n)], 1);
        }
    } else {
        if (e + 3 < E) {
            int4 p = *(const int4*)(w + E + e);
            atomicAdd(&d_cnt[clampi(p.x, n)], 1);
            atomicAdd(&d_cnt[clampi(p.y, n)], 1);
            atomicAdd(&d_cnt[clampi(p.z, n)], 1);
            atomicAdd(&d_cnt[clampi(p.w, n)], 1);
        } else {
            for (int k = e; k < E; k++)
                atomicAdd(&d_cnt[clampi(w[E + k], n)], 1);
        }
    }
}

// Single-pass scan with decoupled lookback. Emits rowstart, cursor, dinv.
__global__ void k_scan(int n) {
    __shared__ int s[SCAN_B];
    __shared__ int s_exc;
    int b = blockIdx.x, t = threadIdx.x;
    int i = b * SCAN_B + t;
    int v = (i < n) ? d_cnt[i] : 0;
    s[t] = v;
    __syncthreads();
    for (int off = 1; off < SCAN_B; off <<= 1) {
        int u = (t >= off) ? s[t - off] : 0;
        __syncthreads();
        s[t] += u;
        __syncthreads();
    }
    if (t == 0) {
        int total = s[SCAN_B - 1];
        volatile unsigned long long* st = (volatile unsigned long long*)d_bstate;
        st[b] = (1ull << 62) | (unsigned long long)total;
        int exc = 0;
        for (int p = b - 1; p >= 0; --p) {
            unsigned long long f;
            do { f = st[p]; } while (f == 0ull);
            exc += (int)(f & 0xffffffffull);
            if ((f >> 62) == 2ull) break;
        }
        st[b] = (2ull << 62) | (unsigned long long)(exc + total);
        s_exc = exc;
    }
    __syncthreads();
    if (i < n) {
        int start = s_exc + s[t] - v;   // exclusive
        d_rowstart[i] = start;
        d_cursor[i] = start;
        d_dinv[i] = rsqrtf((float)v + 1.0f);
    }
}

// GEMM1: gA[i] = dinv[i] * (x[i] @ W1).
// 256 threads / 128 rows per block (2 threads per row, 8 cols each).
// Register-staged pipeline: LDG chunk c+1 overlaps compute of chunk c.
// Packed fma.rn.f32x2 inner loop; conflict-free smem (pad 34, LDS.64 x-reads).
__global__ void __launch_bounds__(G1_THREADS)
k_gemm1(const float* __restrict__ x, const float* __restrict__ W1, int n) {
    __shared__ float W1s[F_IN * HID];                 // 16 KB, [k][j]
    __shared__ float xs[G1_ROWS * XS_PAD];            // 17.75 KB
    int tid = threadIdx.x;
    for (int i = tid; i < F_IN * HID; i += G1_THREADS) W1s[i] = W1[i];
    int row0 = blockIdx.x * G1_ROWS;

    // Staging map: j in 0..3: lin = tid + 256*j; srow = lin>>3; kq = lin&7.
    // Warp covers 4 rows x 8 float4 = 128B contiguous per row.
    float4 st[4];
#pragma unroll
    for (int j = 0; j < 4; j++) {
        int lin = tid + G1_THREADS * j;
        int srow = lin >> 3, kq = lin & 7;
        int grow = row0 + srow; grow = grow < n ? grow : n - 1;
        st[j] = *(const float4*)(x + (long long)grow * F_IN + kq * 4);
    }

    int row = tid >> 1;      // 0..127
    int half = tid & 1;      // cols half*8 .. half*8+7
    unsigned long long acc2[4] = {0ull, 0ull, 0ull, 0ull};

    for (int c = 0; c < G1_CHUNKS; c++) {
        // STS staged chunk (2x STS.64 per float4; offsets always 8B aligned)
#pragma unroll
        for (int j = 0; j < 4; j++) {
            int lin = tid + G1_THREADS * j;
            int srow = lin >> 3, kq = lin & 7;
            float* p = &xs[srow * XS_PAD + kq * 4];
            *(float2*)(p + 0) = make_float2(st[j].x, st[j].y);
            *(float2*)(p + 2) = make_float2(st[j].z, st[j].w);
        }
        __syncthreads();
        if (c + 1 < G1_CHUNKS) {
#pragma unroll
            for (int j = 0; j < 4; j++) {
                int lin = tid + G1_THREADS * j;
                int srow = lin >> 3, kq = lin & 7;
                int grow = row0 + srow; grow = grow < n ? grow : n - 1;
                st[j] = *(const float4*)(x + (long long)grow * F_IN + (c + 1) * G1_KC + kq * 4);
            }
        }
        const float* xb = &xs[row * XS_PAD];
        const float* wb = &W1s[c * G1_KC * HID + half * 8];
#pragma unroll
        for (int k = 0; k < G1_KC; k += 2) {
            float2 xv = *(const float2*)(xb + k);           // LDS.64, conflict-free
            unsigned int xu0 = __float_as_uint(xv.x);
            unsigned int xu1 = __float_as_uint(xv.y);
            unsigned long long xp0, xp1;
            asm("mov.b64 %0, {%1, %1};" : "=l"(xp0) : "r"(xu0));
            asm("mov.b64 %0, {%1, %1};" : "=l"(xp1) : "r"(xu1));
            const ulonglong2* w0 = (const ulonglong2*)(wb + k * HID);        // LDS.128 bcast
            const ulonglong2* w1 = (const ulonglong2*)(wb + (k + 1) * HID);
            ulonglong2 wa = w0[0], wb2 = w0[1];
            ulonglong2 wc = w1[0], wd = w1[1];
            asm("fma.rn.f32x2 %0, %1, %2, %0;" : "+l"(acc2[0]) : "l"(xp0), "l"(wa.x));
            asm("fma.rn.f32x2 %0, %1, %2, %0;" : "+l"(acc2[1]) : "l"(xp0), "l"(wa.y));
            asm("fma.rn.f32x2 %0, %1, %2, %0;" : "+l"(acc2[2]) : "l"(xp0), "l"(wb2.x));
            asm("fma.rn.f32x2 %0, %1, %2, %0;" : "+l"(acc2[3]) : "l"(xp0), "l"(wb2.y));
            asm("fma.rn.f32x2 %0, %1, %2, %0;" : "+l"(acc2[0]) : "l"(xp1), "l"(wc.x));
            asm("fma.rn.f32x2 %0, %1, %2, %0;" : "+l"(acc2[1]) : "l"(xp1), "l"(wc.y));
            asm("fma.rn.f32x2 %0, %1, %2, %0;" : "+l"(acc2[2]) : "l"(xp1), "l"(wd.x));
            asm("fma.rn.f32x2 %0, %1, %2, %0;" : "+l"(acc2[3]) : "l"(xp1), "l"(wd.y));
        }
        __syncthreads();
    }

    int grow = row0 + row;
    if (grow < n) {
        float di = d_dinv[grow];
        float r[8];
#pragma unroll
        for (int j = 0; j < 4; j++) {
            unsigned int lo, hi;
            asm("mov.b64 {%0, %1}, %2;" : "=r"(lo), "=r"(hi) : "l"(acc2[j]));
            r[j * 2 + 0] = di * __uint_as_float(lo);
            r[j * 2 + 1] = di * __uint_as_float(hi);
        }
        float4* g = (float4*)&d_gA[grow * HID + half * 8];
        g[0] = make_float4(r[0], r[1], r[2], r[3]);
        g[1] = make_float4(r[4], r[5], r[6], r[7]);
    }
}

// CSR fill (counting-sort of src by dst), 4 edges per thread.
__global__ void k_fill(const int* __restrict__ w, int E, int n) {
    int t = blockIdx.x * blockDim.x + threadIdx.x;
    int e = t * 4;
    if (e >= E) return;
    if (d_is64) {
        const long long* src = (const long long*)w;
        const long long* dst = src + E;
        if (e + 3 < E) {
            longlong2 s0 = *(const longlong2*)(src + e);
            longlong2 s1 = *(const longlong2*)(src + e + 2);
            longlong2 q0 = *(const longlong2*)(dst + e);
            longlong2 q1 = *(const longlong2*)(dst + e + 2);
            int p0 = atomicAdd(&d_cursor[clampi((int)q0.x, n)], 1);
            int p1 = atomicAdd(&d_cursor[clampi((int)q0.y, n)], 1);
            int p2 = atomicAdd(&d_cursor[clampi((int)q1.x, n)], 1);
            int p3 = atomicAdd(&d_cursor[clampi((int)q1.y, n)], 1);
            d_perm[p0] = clampi((int)s0.x, n);
            d_perm[p1] = clampi((int)s0.y, n);
            d_perm[p2] = clampi((int)s1.x, n);
            d_perm[p3] = clampi((int)s1.y, n);
        } else {
            for (int k = e; k < E; k++) {
                int p = atomicAdd(&d_cursor[clampi((int)dst[k], n)], 1);
                d_perm[p] = clampi((int)src[k], n);
            }
        }
    } else {
        if (e + 3 < E) {
            int4 sv = *(const int4*)(w + e);
            int4 dv = *(const int4*)(w + E + e);
            int p0 = atomicAdd(&d_cursor[clampi(dv.x, n)], 1);
            int p1 = atomicAdd(&d_cursor[clampi(dv.y, n)], 1);
            int p2 = atomicAdd(&d_cursor[clampi(dv.z, n)], 1);
            int p3 = atomicAdd(&d_cursor[clampi(dv.w, n)], 1);
            d_perm[p0] = clampi(sv.x, n);
            d_perm[p1] = clampi(sv.y, n);
            d_perm[p2] = clampi(sv.z, n);
            d_perm[p3] = clampi(sv.w, n);
        } else {
            for (int k = e; k < E; k++) {
                int p = atomicAdd(&d_cursor[clampi(w[E + k], n)], 1);
                d_perm[p] = clampi(w[k], n);
            }
        }
    }
}

// Layer-1 gather: 4 threads/node; gB = dinv * relu(dinv*acc + b1).
__global__ void k_gather0(const float* __restrict__ b1, int n) {
    int idx = blockIdx.x * blockDim.x + threadIdx.x;
    if (idx >= n * 4) return;
    int node = idx >> 2, q = idx & 3;
    const float4* __restrict__ g4 = (const float4*)d_gA;

    float4 acc = g4[node * 4 + q];  // self-loop
    int start = d_rowstart[node];
    int end = start + d_cnt[node];
#pragma unroll 8
    for (int j = start; j < end; j++) {
        int s = __ldg(&d_perm[j]);
        float4 v = g4[s * 4 + q];
        acc.x += v.x; acc.y += v.y; acc.z += v.z; acc.w += v.w;
    }

    float di = d_dinv[node];
    float4 b = ((const float4*)b1)[q];
    float4 h;
    h.x = di * fmaxf(fmaf(di, acc.x, b.x), 0.f);
    h.y = di * fmaxf(fmaf(di, acc.y, b.y), 0.f);
    h.z = di * fmaxf(fmaf(di, acc.z, b.z), 0.f);
    h.w = di * fmaxf(fmaf(di, acc.w, b.w), 0.f);
    ((float4*)d_gB)[idx] = h;
}

// Layer-2 gather fused with logits + log_softmax.
__global__ void k_gather1_final(const float* __restrict__ W2, const float* __restrict__ b2,
                                float* __restrict__ out, int n) {
    __shared__ float W2s[HID * NC];
    __shared__ float b2s[NC];
    __shared__ float hs[64 * 17];       // 64 nodes/block, padded stride 17
    int tid = threadIdx.x;
    for (int i = tid; i < HID * NC; i += 256) W2s[i] = W2[i];
    if (tid < NC) b2s[tid] = b2[tid];

    int idx = blockIdx.x * 256 + tid;
    int node = idx >> 2, q = idx & 3;
    int ln = tid >> 2;                  // local node 0..63

    if (node < n) {
        const float4* __restrict__ g4 = (const float4*)d_gB;
        float4 acc = g4[node * 4 + q];  // self-loop
        int start = d_rowstart[node];
        int end = start + d_cnt[node];
#pragma unroll 8
        for (int j = start; j < end; j++) {
            int s = __ldg(&d_perm[j]);
            float4 v = g4[s * 4 + q];
            acc.x += v.x; acc.y += v.y; acc.z += v.z; acc.w += v.w;
        }
        float di = d_dinv[node];
        hs[ln * 17 + q * 4 + 0] = di * acc.x;
        hs[ln * 17 + q * 4 + 1] = di * acc.y;
        hs[ln * 17 + q * 4 + 2] = di * acc.z;
        hs[ln * 17 + q * 4 + 3] = di * acc.w;
    }
    __syncthreads();

    float p[HID];
#pragma unroll
    for (int k = 0; k < HID; k++) p[k] = hs[ln * 17 + k];

    float l[10];
#pragma unroll
    for (int j = 0; j < 10; j++) {
        int col = q * 10 + j;
        float a = b2s[col];
#pragma unroll
        for (int k = 0; k < HID; k++) a = fmaf(p[k], W2s[k * NC + col], a);
        l[j] = a;
    }
    float m = l[0];
#pragma unroll
    for (int j = 1; j < 10; j++) m = fmaxf(m, l[j]);
    m = fmaxf(m, __shfl_xor_sync(0xffffffffu, m, 1));
    m = fmaxf(m, __shfl_xor_sync(0xffffffffu, m, 2));
    float s = 0.f;
#pragma unroll
    for (int j = 0; j < 10; j++) s += __expf(l[j] - m);
    s += __shfl_xor_sync(0xffffffffu, s, 1);
    s += __shfl_xor_sync(0xffffffffu, s, 2);
    float lse = m + __logf(s);

    if (node < n) {
        float* o = out + (long long)node * NC + q * 10;
#pragma unroll
        for (int j = 0; j < 10; j++) o[j] = l[j] - lse;
    }
}

extern "C" void kernel_launch(void* const* d_in, const int* in_sizes, int n_in,
                              void* d_out, int out_size) {
    const float* x   = (const float*)d_in[0];
    const int*   eiw = (const int*)d_in[1];   // raw words; layout detected on device
    const float* W1  = (const float*)d_in[2];
    const float* b1  = (const float*)d_in[3];
    const float* W2  = (const float*)d_in[4];
    const float* b2  = (const float*)d_in[5];
    float* out = (float*)d_out;

    int n = in_sizes[0] / F_IN;        // 100000
    int E = in_sizes[1] / 2;           // 3200000
    int nwords = in_sizes[1] * 2;
    int eh = (E + 3) / 4;              // 4 edges/thread
    int nb = (n + SCAN_B - 1) / SCAN_B;   // 391 <= NB_MAX

    k_init  <<<(n + 255) / 256, 256>>>(eiw, nwords, n);            // 0
    k_hist  <<<(eh + 255) / 256, 256>>>(eiw, E, n);                // 1
    k_scan  <<<nb, SCAN_B>>>(n);                                    // 2
    k_gemm1 <<<(n + G1_ROWS - 1) / G1_ROWS, G1_THREADS>>>(x, W1, n); // 3 <- ncu
    k_fill  <<<(eh + 255) / 256, 256>>>(eiw, E, n);                // 4
    k_gather0<<<(n * 4 + 255) / 256, 256>>>(b1, n);                // 5
    k_gather1_final<<<(n * 4 + 255) / 256, 256>>>(W2, b2, out, n); // 6
}